// round 11
// baseline (speedup 1.0000x reference)
#include <cuda_runtime.h>
#include <math.h>

// ---------------------------------------------------------------------------
// ERBM CD-1 sweep, bit-matched to JAX (threefry2x32, partitionable RNG).
//
// Inputs (metadata order):
//   d_in[0] biadj  f32 [64,64,8]
//   d_in[1] eps    f32 [8,3,2,2]
//   d_in[2] chi    f32 [4,4,3]
//   d_in[3] x0_idx i32 [65536,128]
// Output: [loss(1), x(65536*128*4)] f32 (layout detected from out_size).
//
// R6: borderline argmaxes (top-2 score gap < 1e-2) are recomputed with exact
// TwoSum compensated summation, making every decision match the true-value
// argmax. Fast path unchanged. Gumbel back on plain logf (R4==R5 proved the
// log path is decision-equivalent).
// ---------------------------------------------------------------------------

#define S_TOTAL 65536
#define XDIM 128
#define ZDIM 128
#define S_TILE 128
#define CHUNK 16
#define NCHUNK 8
#define NBLK (S_TOTAL / S_TILE)
#define GAP_THR 1e-2f

// K in two gather-friendly layouts:
//   g_Kz[((z*128 + x)*4 + a)*4 + b]   (z-stage: gather over a, vector over b)
//   g_Kx[((x*128 + z)*4 + b)*4 + a]   (x-stage: gather over b, vector over a)
__device__ float g_Kz[ZDIM * XDIM * 16];
__device__ float g_Kx[XDIM * ZDIM * 16];
__device__ unsigned char g_zidx[(size_t)S_TOTAL * ZDIM];
__device__ double g_blocksum[NBLK];

// ---------------------------------------------------------------------------
// threefry2x32 (JAX/Random123, 20 rounds)
// ---------------------------------------------------------------------------
__host__ __device__ __forceinline__ void tf2x32(unsigned k0, unsigned k1,
                                                unsigned c0, unsigned c1,
                                                unsigned& o0, unsigned& o1) {
  unsigned ks2 = k0 ^ k1 ^ 0x1BD11BDAu;
  unsigned x0 = c0 + k0, x1 = c1 + k1;
#define TF_R(r) { x0 += x1; x1 = (x1 << (r)) | (x1 >> (32 - (r))); x1 ^= x0; }
  TF_R(13) TF_R(15) TF_R(26) TF_R(6)
  x0 += k1;  x1 += ks2 + 1u;
  TF_R(17) TF_R(29) TF_R(16) TF_R(24)
  x0 += ks2; x1 += k0 + 2u;
  TF_R(13) TF_R(15) TF_R(26) TF_R(6)
  x0 += k0;  x1 += k1 + 3u;
  TF_R(17) TF_R(29) TF_R(16) TF_R(24)
  x0 += k1;  x1 += ks2 + 4u;
  TF_R(13) TF_R(15) TF_R(26) TF_R(6)
  x0 += ks2; x1 += k0 + 5u;
#undef TF_R
  o0 = x0; o1 = x1;
}

// JAX partitionable 32-bit random bits for flat index idx (< 2^32 here):
// counter = (hi=0, lo=idx), bits = out0 ^ out1. Then JAX uniform + gumbel.
__device__ __forceinline__ float jax_gumbel(unsigned k0, unsigned k1, unsigned idx) {
  unsigned o0, o1;
  tf2x32(k0, k1, 0u, idx, o0, o1);
  unsigned bits = o0 ^ o1;
  float u = __uint_as_float(0x3f800000u | (bits >> 9)) - 1.0f;
  u = fmaxf(u, 1.1754943508222875e-38f);  // minval = float32 tiny
  return -logf(-logf(u));
}

// TwoSum step: exact error-compensated accumulation (adds/subs only, so no
// fma contraction can break it).
__device__ __forceinline__ void two_sum(float& hi, float& lo, float v) {
  float s = hi + v;
  float bv = s - hi;
  float err = (hi - (s - bv)) + (v - bv);
  lo += err;
  hi = s;
}

// ---------------------------------------------------------------------------
// Kernel 1: build K = tensordot(tensordot(biadj, eps), chi), sequential fmaf
// chains matching the reference contraction order (bond 0..7, then k 0..2).
// ---------------------------------------------------------------------------
__global__ void build_kernel(const float* __restrict__ biadj,
                             const float* __restrict__ eps,
                             const float* __restrict__ chi) {
  int t = blockIdx.x * blockDim.x + threadIdx.x;
  if (t >= XDIM * ZDIM) return;
  int X = t >> 7, Z = t & 127;
  int lx = X >> 1, dx = X & 1, lz = Z >> 1, dz = Z & 1;
  float c[3];
#pragma unroll
  for (int k = 0; k < 3; k++) {
    float acc = 0.f;
#pragma unroll
    for (int b = 0; b < 8; b++)
      acc = fmaf(biadj[(lx * 64 + lz) * 8 + b],
                 eps[((b * 3 + k) * 2 + dx) * 2 + dz], acc);
    c[k] = acc;
  }
#pragma unroll
  for (int a = 0; a < 4; a++)
#pragma unroll
    for (int b = 0; b < 4; b++) {
      float v = 0.f;
#pragma unroll
      for (int k = 0; k < 3; k++) v = fmaf(c[k], chi[(a * 4 + b) * 3 + k], v);
      g_Kz[((Z * 128 + X) * 4 + a) * 4 + b] = v;
      g_Kx[((X * 128 + Z) * 4 + b) * 4 + a] = v;
    }
}

// ---------------------------------------------------------------------------
// Kernel 2: z-stage. Block = 128 samples. Chunks of 16 z in smem.
// thread = (s_local = t&127, g = t>>7); g owns 4 z's of the chunk.
// ez accumulated sequentially over x = 0..127; borderline argmaxes redone
// with exact TwoSum.
// ---------------------------------------------------------------------------
__global__ __launch_bounds__(512) void z_kernel(const int* __restrict__ x0_idx,
                                                unsigned kz0, unsigned kz1) {
  extern __shared__ unsigned char smem[];
  float* sK = (float*)smem;                       // 131072 B
  unsigned char* sIdx = smem + 131072;            // 16384 B: [x][s_local]
  int t = threadIdx.x;
  int s0 = blockIdx.x * S_TILE;

  for (int j = t; j < S_TILE * XDIM; j += 512) {
    int i = j >> 7, x = j & 127;
    sIdx[x * S_TILE + i] = (unsigned char)(x0_idx[(s0 + i) * XDIM + x] & 3);
  }

  int s_local = t & 127, g = t >> 7;
  int s = s0 + s_local;

  for (int c = 0; c < NCHUNK; c++) {
    __syncthreads();
    {
      const float4* src = (const float4*)(g_Kz + (size_t)c * CHUNK * XDIM * 16);
      float4* dst = (float4*)sK;
      for (int j = t; j < CHUNK * XDIM * 4; j += 512) dst[j] = src[j];
    }
    __syncthreads();

    float4 acc[4] = {{0.f,0.f,0.f,0.f},{0.f,0.f,0.f,0.f},
                     {0.f,0.f,0.f,0.f},{0.f,0.f,0.f,0.f}};
    int zbase = g * 4;
#pragma unroll 4
    for (int x = 0; x < XDIM; x++) {
      int a = sIdx[x * S_TILE + s_local];
      const float* rowp = sK + x * 16 + a * 4;
#pragma unroll
      for (int zz = 0; zz < 4; zz++) {
        float4 v = *(const float4*)(rowp + (zbase + zz) * (XDIM * 16));
        acc[zz].x += v.x; acc[zz].y += v.y; acc[zz].z += v.z; acc[zz].w += v.w;
      }
    }

#pragma unroll
    for (int zz = 0; zz < 4; zz++) {
      int z = c * CHUNK + zbase + zz;
      float ez[4] = {acc[zz].x, acc[zz].y, acc[zz].z, acc[zz].w};
      unsigned base = ((unsigned)(s * ZDIM + z)) * 4u;
      float gq[4], sc[4];
#pragma unroll
      for (int b = 0; b < 4; b++) {
        gq[b] = jax_gumbel(kz0, kz1, base + (unsigned)b);
        sc[b] = gq[b] - ez[b];
      }
      int bi = 0;
#pragma unroll
      for (int b = 1; b < 4; b++) if (sc[b] > sc[bi]) bi = b;
      float second = -3.4e38f;
#pragma unroll
      for (int b = 0; b < 4; b++) if (b != bi && sc[b] > second) second = sc[b];

      if (sc[bi] - second < GAP_THR) {
        // exact recompute via TwoSum over x (rare)
        float hi[4] = {0.f,0.f,0.f,0.f}, lo[4] = {0.f,0.f,0.f,0.f};
        for (int x = 0; x < XDIM; x++) {
          int a = sIdx[x * S_TILE + s_local];
          const float* p = sK + (zbase + zz) * (XDIM * 16) + x * 16 + a * 4;
#pragma unroll
          for (int b = 0; b < 4; b++) two_sum(hi[b], lo[b], p[b]);
        }
        float sce[4];
#pragma unroll
        for (int b = 0; b < 4; b++) sce[b] = gq[b] - (hi[b] + lo[b]);
        bi = 0;
#pragma unroll
        for (int b = 1; b < 4; b++) if (sce[b] > sce[bi]) bi = b;
      }
      g_zidx[(size_t)s * ZDIM + z] = (unsigned char)bi;
    }
  }
}

// ---------------------------------------------------------------------------
// Kernel 3: x-stage. Same structure over x-chunks; gather index is z_idx.
// Writes one-hot x and the per-block loss partial (deterministic).
// ---------------------------------------------------------------------------
__global__ __launch_bounds__(512) void x_kernel(const int* __restrict__ x0_idx,
                                                float* __restrict__ out_x,
                                                int write_x, int has_loss,
                                                unsigned kx0, unsigned kx1) {
  extern __shared__ unsigned char smem[];
  float* sK = (float*)smem;                       // 131072 B
  unsigned char* sZ = smem + 131072;              // 16384 B: [z][s_local]
  int t = threadIdx.x;
  int s0 = blockIdx.x * S_TILE;

  for (int j = t; j < S_TILE * ZDIM; j += 512) {
    int i = j >> 7, z = j & 127;
    sZ[z * S_TILE + i] = g_zidx[(size_t)(s0 + i) * ZDIM + z];
  }

  int s_local = t & 127, g = t >> 7;
  int s = s0 + s_local;
  double lsum = 0.0;

  for (int c = 0; c < NCHUNK; c++) {
    __syncthreads();
    {
      const float4* src = (const float4*)(g_Kx + (size_t)c * CHUNK * ZDIM * 16);
      float4* dst = (float4*)sK;
      for (int j = t; j < CHUNK * ZDIM * 4; j += 512) dst[j] = src[j];
    }
    __syncthreads();

    float4 acc[4] = {{0.f,0.f,0.f,0.f},{0.f,0.f,0.f,0.f},
                     {0.f,0.f,0.f,0.f},{0.f,0.f,0.f,0.f}};
    int xbase = g * 4;
#pragma unroll 4
    for (int z = 0; z < ZDIM; z++) {
      int b = sZ[z * S_TILE + s_local];
      const float* rowp = sK + z * 16 + b * 4;
#pragma unroll
      for (int xx = 0; xx < 4; xx++) {
        float4 v = *(const float4*)(rowp + (xbase + xx) * (ZDIM * 16));
        acc[xx].x += v.x; acc[xx].y += v.y; acc[xx].z += v.z; acc[xx].w += v.w;
      }
    }

#pragma unroll
    for (int xx = 0; xx < 4; xx++) {
      int x = c * CHUNK + xbase + xx;
      float ex[4] = {acc[xx].x, acc[xx].y, acc[xx].z, acc[xx].w};
      unsigned base = ((unsigned)(s * XDIM + x)) * 4u;
      float gq[4], sc[4];
#pragma unroll
      for (int a = 0; a < 4; a++) {
        gq[a] = jax_gumbel(kx0, kx1, base + (unsigned)a);
        sc[a] = gq[a] - ex[a];
      }
      int a1 = 0;
#pragma unroll
      for (int a = 1; a < 4; a++) if (sc[a] > sc[a1]) a1 = a;
      float second = -3.4e38f;
#pragma unroll
      for (int a = 0; a < 4; a++) if (a != a1 && sc[a] > second) second = sc[a];

      if (sc[a1] - second < GAP_THR) {
        float hi[4] = {0.f,0.f,0.f,0.f}, lo[4] = {0.f,0.f,0.f,0.f};
        for (int z = 0; z < ZDIM; z++) {
          int b = sZ[z * S_TILE + s_local];
          const float* p = sK + (xbase + xx) * (ZDIM * 16) + z * 16 + b * 4;
#pragma unroll
          for (int a = 0; a < 4; a++) two_sum(hi[a], lo[a], p[a]);
        }
        float sce[4];
#pragma unroll
        for (int a = 0; a < 4; a++) {
          ex[a] = hi[a] + lo[a];
          sce[a] = gq[a] - ex[a];
        }
        a1 = 0;
#pragma unroll
        for (int a = 1; a < 4; a++) if (sce[a] > sce[a1]) a1 = a;
      }

      if (write_x) {
        float* o = out_x + ((size_t)(s * XDIM + x)) * 4;
        o[0] = (a1 == 0) ? 1.f : 0.f;
        o[1] = (a1 == 1) ? 1.f : 0.f;
        o[2] = (a1 == 2) ? 1.f : 0.f;
        o[3] = (a1 == 3) ? 1.f : 0.f;
      }
      if (has_loss) {
        int a0 = x0_idx[s * XDIM + x] & 3;
        lsum += (double)(ex[a0] - ex[a1]);  // == sum_a ex*(x0-x)
      }
    }
  }

  if (has_loss) {
    __syncthreads();
    double* red = (double*)smem;  // reuse sK region
    red[t] = lsum;
    __syncthreads();
    for (int st = 256; st > 0; st >>= 1) {
      if (t < st) red[t] += red[t + st];
      __syncthreads();
    }
    if (t == 0) g_blocksum[blockIdx.x] = red[0];
  }
}

__global__ void fin_kernel(float* out) {
  double ssum = 0.0;
  for (int i = 0; i < NBLK; i++) ssum += g_blocksum[i];
  out[0] = (float)(ssum / 65536.0);
}

// ---------------------------------------------------------------------------
extern "C" void kernel_launch(void* const* d_in, const int* in_sizes, int n_in,
                              void* d_out, int out_size) {
  const float* biadj = (const float*)d_in[0];
  const float* eps   = (const float*)d_in[1];
  const float* chi   = (const float*)d_in[2];
  const int*   idx   = (const int*)d_in[3];
  float* out = (float*)d_out;

  // keys: fold-like split of key(42) = (0, 42): kz = TF(key,(0,0)), kx = TF(key,(0,1))
  unsigned kz0, kz1, kx0, kx1;
  tf2x32(0u, 42u, 0u, 0u, kz0, kz1);
  tf2x32(0u, 42u, 0u, 1u, kx0, kx1);

  const long long x_elems = (long long)S_TOTAL * XDIM * 4;
  int has_loss = (out_size != (int)x_elems);
  int write_x  = ((long long)out_size >= x_elems);
  float* out_x = (has_loss && write_x) ? out + 1 : out;

  cudaFuncSetAttribute((const void*)z_kernel,
                       cudaFuncAttributeMaxDynamicSharedMemorySize, 147456);
  cudaFuncSetAttribute((const void*)x_kernel,
                       cudaFuncAttributeMaxDynamicSharedMemorySize, 147456);

  build_kernel<<<64, 256>>>(biadj, eps, chi);
  z_kernel<<<NBLK, 512, 147456>>>(idx, kz0, kz1);
  x_kernel<<<NBLK, 512, 147456>>>(idx, out_x, write_x, has_loss, kx0, kx1);
  if (has_loss) fin_kernel<<<1, 1>>>(out);
}

// round 15
// speedup vs baseline: 1.0432x; 1.0432x over previous
#include <cuda_runtime.h>
#include <math.h>

// ---------------------------------------------------------------------------
// ERBM CD-1 sweep, bit-matched to JAX (threefry2x32, partitionable RNG).
// R11: packed f32x2 accumulation (bit-identical rounding), CHUNK=8 for
// 2 CTAs/SM, coalesced one-hot writes via smem code buffer, parallel loss
// finalize. Decision logic (threefry, gumbel logf, TwoSum fallback) frozen.
// ---------------------------------------------------------------------------

#define S_TOTAL 65536
#define XDIM 128
#define ZDIM 128
#define S_TILE 128
#define CHUNK 8
#define NCHUNK 16
#define ZPG 2                       // outputs per group per chunk (CHUNK/4)
#define NBLK (S_TOTAL / S_TILE)
#define GAP_THR 1e-2f

#define SK_BYTES (CHUNK * 128 * 16 * 4)     // 65536
#define SIDX_OFF SK_BYTES                   // byte idx buffer [x][s_local]
#define SCODE_OFF (SK_BYTES + 16384)        // 81920 (x_kernel only)
#define CODE_PITCH 132
#define SMEM_Z (SK_BYTES + 16384)                   // 81920
#define SMEM_X (SK_BYTES + 16384 + 128 * CODE_PITCH) // 98816

__device__ float g_Kz[ZDIM * XDIM * 16];  // [((z*128+x)*4+a)*4+b]
__device__ float g_Kx[XDIM * ZDIM * 16];  // [((x*128+z)*4+b)*4+a]
__device__ unsigned char g_zidx[(size_t)S_TOTAL * ZDIM];
__device__ double g_blocksum[NBLK];

// packed dual f32 add, round-to-nearest per lane: bit-identical to 2x FADD.RN
__device__ __forceinline__ void padd(unsigned long long& a, unsigned long long b) {
  asm("add.rn.f32x2 %0, %0, %1;" : "+l"(a) : "l"(b));
}
__device__ __forceinline__ float plo(unsigned long long a) {
  return __uint_as_float((unsigned)a);
}
__device__ __forceinline__ float phi(unsigned long long a) {
  return __uint_as_float((unsigned)(a >> 32));
}

// ---------------------------------------------------------------------------
// threefry2x32 (JAX/Random123, 20 rounds)
// ---------------------------------------------------------------------------
__host__ __device__ __forceinline__ void tf2x32(unsigned k0, unsigned k1,
                                                unsigned c0, unsigned c1,
                                                unsigned& o0, unsigned& o1) {
  unsigned ks2 = k0 ^ k1 ^ 0x1BD11BDAu;
  unsigned x0 = c0 + k0, x1 = c1 + k1;
#define TF_R(r) { x0 += x1; x1 = (x1 << (r)) | (x1 >> (32 - (r))); x1 ^= x0; }
  TF_R(13) TF_R(15) TF_R(26) TF_R(6)
  x0 += k1;  x1 += ks2 + 1u;
  TF_R(17) TF_R(29) TF_R(16) TF_R(24)
  x0 += ks2; x1 += k0 + 2u;
  TF_R(13) TF_R(15) TF_R(26) TF_R(6)
  x0 += k0;  x1 += k1 + 3u;
  TF_R(17) TF_R(29) TF_R(16) TF_R(24)
  x0 += k1;  x1 += ks2 + 4u;
  TF_R(13) TF_R(15) TF_R(26) TF_R(6)
  x0 += ks2; x1 += k0 + 5u;
#undef TF_R
  o0 = x0; o1 = x1;
}

__device__ __forceinline__ float jax_gumbel(unsigned k0, unsigned k1, unsigned idx) {
  unsigned o0, o1;
  tf2x32(k0, k1, 0u, idx, o0, o1);
  unsigned bits = o0 ^ o1;
  float u = __uint_as_float(0x3f800000u | (bits >> 9)) - 1.0f;
  u = fmaxf(u, 1.1754943508222875e-38f);
  return -logf(-logf(u));
}

__device__ __forceinline__ void two_sum(float& hi, float& lo, float v) {
  float s = hi + v;
  float bv = s - hi;
  float err = (hi - (s - bv)) + (v - bv);
  lo += err;
  hi = s;
}

// ---------------------------------------------------------------------------
__global__ void build_kernel(const float* __restrict__ biadj,
                             const float* __restrict__ eps,
                             const float* __restrict__ chi) {
  int t = blockIdx.x * blockDim.x + threadIdx.x;
  if (t >= XDIM * ZDIM) return;
  int X = t >> 7, Z = t & 127;
  int lx = X >> 1, dx = X & 1, lz = Z >> 1, dz = Z & 1;
  float c[3];
#pragma unroll
  for (int k = 0; k < 3; k++) {
    float acc = 0.f;
#pragma unroll
    for (int b = 0; b < 8; b++)
      acc = fmaf(biadj[(lx * 64 + lz) * 8 + b],
                 eps[((b * 3 + k) * 2 + dx) * 2 + dz], acc);
    c[k] = acc;
  }
#pragma unroll
  for (int a = 0; a < 4; a++)
#pragma unroll
    for (int b = 0; b < 4; b++) {
      float v = 0.f;
#pragma unroll
      for (int k = 0; k < 3; k++) v = fmaf(c[k], chi[(a * 4 + b) * 3 + k], v);
      g_Kz[((Z * 128 + X) * 4 + a) * 4 + b] = v;
      g_Kx[((X * 128 + Z) * 4 + b) * 4 + a] = v;
    }
}

// ---------------------------------------------------------------------------
// z-stage: block = 128 samples, chunks of 8 z. Reduction over x = 0..127 is
// strictly sequential (order identical to previous passing kernel).
// ---------------------------------------------------------------------------
__global__ __launch_bounds__(512, 2) void z_kernel(const int* __restrict__ x0_idx,
                                                   unsigned kz0, unsigned kz1) {
  extern __shared__ unsigned char smem[];
  float* sK = (float*)smem;
  unsigned char* sIdx = smem + SIDX_OFF;   // [x][s_local], values a*16 (byte off)
  int t = threadIdx.x;
  int s0 = blockIdx.x * S_TILE;

  for (int j = t; j < S_TILE * XDIM; j += 512) {
    int i = j >> 7, x = j & 127;
    sIdx[x * S_TILE + i] = (unsigned char)((x0_idx[(s0 + i) * XDIM + x] & 3) * 16);
  }

  int s_local = t & 127, g = t >> 7;
  int s = s0 + s_local;

  for (int c = 0; c < NCHUNK; c++) {
    __syncthreads();
    {
      const float4* src = (const float4*)(g_Kz + (size_t)c * CHUNK * XDIM * 16);
      float4* dst = (float4*)sK;
      for (int j = t; j < CHUNK * XDIM * 4; j += 512) dst[j] = src[j];
    }
    __syncthreads();

    int zc0 = g * ZPG, zc1 = zc0 + 1;
    const char* b0 = (const char*)sK + zc0 * (XDIM * 64);
    const char* b1 = (const char*)sK + zc1 * (XDIM * 64);
    unsigned long long a00 = 0, a01 = 0, a10 = 0, a11 = 0;
#pragma unroll 4
    for (int x = 0; x < XDIM; x++) {
      int a4 = sIdx[x * S_TILE + s_local];
      ulonglong2 v0 = *(const ulonglong2*)(b0 + x * 64 + a4);
      ulonglong2 v1 = *(const ulonglong2*)(b1 + x * 64 + a4);
      padd(a00, v0.x); padd(a01, v0.y);
      padd(a10, v1.x); padd(a11, v1.y);
    }

#pragma unroll
    for (int zz = 0; zz < ZPG; zz++) {
      int zc = g * ZPG + zz;
      int z = c * CHUNK + zc;
      float ez[4];
      if (zz == 0) { ez[0] = plo(a00); ez[1] = phi(a00); ez[2] = plo(a01); ez[3] = phi(a01); }
      else         { ez[0] = plo(a10); ez[1] = phi(a10); ez[2] = plo(a11); ez[3] = phi(a11); }
      unsigned base = ((unsigned)(s * ZDIM + z)) * 4u;
      float gq[4], sc[4];
#pragma unroll
      for (int b = 0; b < 4; b++) {
        gq[b] = jax_gumbel(kz0, kz1, base + (unsigned)b);
        sc[b] = gq[b] - ez[b];
      }
      int bi = 0;
#pragma unroll
      for (int b = 1; b < 4; b++) if (sc[b] > sc[bi]) bi = b;
      float second = -3.4e38f;
#pragma unroll
      for (int b = 0; b < 4; b++) if (b != bi && sc[b] > second) second = sc[b];

      if (sc[bi] - second < GAP_THR) {
        float hi[4] = {0.f,0.f,0.f,0.f}, lo[4] = {0.f,0.f,0.f,0.f};
        const char* bb = (const char*)sK + zc * (XDIM * 64);
        for (int x = 0; x < XDIM; x++) {
          int a4 = sIdx[x * S_TILE + s_local];
          const float* p = (const float*)(bb + x * 64 + a4);
#pragma unroll
          for (int b = 0; b < 4; b++) two_sum(hi[b], lo[b], p[b]);
        }
        float sce[4];
#pragma unroll
        for (int b = 0; b < 4; b++) sce[b] = gq[b] - (hi[b] + lo[b]);
        bi = 0;
#pragma unroll
        for (int b = 1; b < 4; b++) if (sce[b] > sce[bi]) bi = b;
      }
      g_zidx[(size_t)s * ZDIM + z] = (unsigned char)bi;
    }
  }
}

// ---------------------------------------------------------------------------
// x-stage: mirrors z-stage; codes staged in smem, coalesced one-hot write.
// ---------------------------------------------------------------------------
__global__ __launch_bounds__(512, 2) void x_kernel(const int* __restrict__ x0_idx,
                                                   float* __restrict__ out_x,
                                                   int write_x, int has_loss,
                                                   unsigned kx0, unsigned kx1) {
  extern __shared__ unsigned char smem[];
  float* sK = (float*)smem;
  unsigned char* sZ = smem + SIDX_OFF;     // [z][s_local], values b*16
  unsigned char* sCode = smem + SCODE_OFF; // [s_local][x], pitch 132
  int t = threadIdx.x;
  int s0 = blockIdx.x * S_TILE;

  for (int j = t; j < S_TILE * ZDIM; j += 512) {
    int i = j >> 7, z = j & 127;
    sZ[z * S_TILE + i] = (unsigned char)(g_zidx[(size_t)(s0 + i) * ZDIM + z] * 16);
  }

  int s_local = t & 127, g = t >> 7;
  int s = s0 + s_local;
  double lsum = 0.0;

  for (int c = 0; c < NCHUNK; c++) {
    __syncthreads();
    {
      const float4* src = (const float4*)(g_Kx + (size_t)c * CHUNK * ZDIM * 16);
      float4* dst = (float4*)sK;
      for (int j = t; j < CHUNK * ZDIM * 4; j += 512) dst[j] = src[j];
    }
    __syncthreads();

    int xc0 = g * ZPG, xc1 = xc0 + 1;
    const char* b0 = (const char*)sK + xc0 * (ZDIM * 64);
    const char* b1 = (const char*)sK + xc1 * (ZDIM * 64);
    unsigned long long a00 = 0, a01 = 0, a10 = 0, a11 = 0;
#pragma unroll 4
    for (int z = 0; z < ZDIM; z++) {
      int b4 = sZ[z * S_TILE + s_local];
      ulonglong2 v0 = *(const ulonglong2*)(b0 + z * 64 + b4);
      ulonglong2 v1 = *(const ulonglong2*)(b1 + z * 64 + b4);
      padd(a00, v0.x); padd(a01, v0.y);
      padd(a10, v1.x); padd(a11, v1.y);
    }

#pragma unroll
    for (int xx = 0; xx < ZPG; xx++) {
      int xc = g * ZPG + xx;
      int x = c * CHUNK + xc;
      float ex[4];
      if (xx == 0) { ex[0] = plo(a00); ex[1] = phi(a00); ex[2] = plo(a01); ex[3] = phi(a01); }
      else         { ex[0] = plo(a10); ex[1] = phi(a10); ex[2] = plo(a11); ex[3] = phi(a11); }
      unsigned base = ((unsigned)(s * XDIM + x)) * 4u;
      float gq[4], sc[4];
#pragma unroll
      for (int a = 0; a < 4; a++) {
        gq[a] = jax_gumbel(kx0, kx1, base + (unsigned)a);
        sc[a] = gq[a] - ex[a];
      }
      int a1 = 0;
#pragma unroll
      for (int a = 1; a < 4; a++) if (sc[a] > sc[a1]) a1 = a;
      float second = -3.4e38f;
#pragma unroll
      for (int a = 0; a < 4; a++) if (a != a1 && sc[a] > second) second = sc[a];

      if (sc[a1] - second < GAP_THR) {
        float hi[4] = {0.f,0.f,0.f,0.f}, lo[4] = {0.f,0.f,0.f,0.f};
        const char* bb = (const char*)sK + xc * (ZDIM * 64);
        for (int z = 0; z < ZDIM; z++) {
          int b4 = sZ[z * S_TILE + s_local];
          const float* p = (const float*)(bb + z * 64 + b4);
#pragma unroll
          for (int a = 0; a < 4; a++) two_sum(hi[a], lo[a], p[a]);
        }
        float sce[4];
#pragma unroll
        for (int a = 0; a < 4; a++) {
          ex[a] = hi[a] + lo[a];
          sce[a] = gq[a] - ex[a];
        }
        a1 = 0;
#pragma unroll
        for (int a = 1; a < 4; a++) if (sce[a] > sce[a1]) a1 = a;
      }

      sCode[s_local * CODE_PITCH + x] = (unsigned char)a1;
      if (has_loss) {
        int a0 = x0_idx[s * XDIM + x] & 3;
        lsum += (double)(ex[a0] - ex[a1]);
      }
    }
  }

  __syncthreads();  // codes complete; sK no longer needed

  if (write_x) {
    // coalesced: consecutive lanes -> consecutive x within a sample row
    for (int j = t; j < S_TILE * XDIM; j += 512) {
      int sl = j >> 7, x = j & 127;
      int code = sCode[sl * CODE_PITCH + x];
      float* o = out_x + ((size_t)((s0 + sl) * XDIM + x)) * 4;
      o[0] = (code == 0) ? 1.f : 0.f;
      o[1] = (code == 1) ? 1.f : 0.f;
      o[2] = (code == 2) ? 1.f : 0.f;
      o[3] = (code == 3) ? 1.f : 0.f;
    }
  }

  if (has_loss) {
    double* red = (double*)smem;  // overlays sK (done)
    red[t] = lsum;
    __syncthreads();
    for (int st = 256; st > 0; st >>= 1) {
      if (t < st) red[t] += red[t + st];
      __syncthreads();
    }
    if (t == 0) g_blocksum[blockIdx.x] = red[0];
  }
}

__global__ void fin_kernel(float* __restrict__ out) {
  __shared__ double red[NBLK];
  int t = threadIdx.x;
  red[t] = g_blocksum[t];
  __syncthreads();
  for (int st = NBLK / 2; st > 0; st >>= 1) {
    if (t < st) red[t] += red[t + st];
    __syncthreads();
  }
  if (t == 0) out[0] = (float)(red[0] / 65536.0);
}

// ---------------------------------------------------------------------------
extern "C" void kernel_launch(void* const* d_in, const int* in_sizes, int n_in,
                              void* d_out, int out_size) {
  const float* biadj = (const float*)d_in[0];
  const float* eps   = (const float*)d_in[1];
  const float* chi   = (const float*)d_in[2];
  const int*   idx   = (const int*)d_in[3];
  float* out = (float*)d_out;

  unsigned kz0, kz1, kx0, kx1;
  tf2x32(0u, 42u, 0u, 0u, kz0, kz1);
  tf2x32(0u, 42u, 0u, 1u, kx0, kx1);

  const long long x_elems = (long long)S_TOTAL * XDIM * 4;
  int has_loss = (out_size != (int)x_elems);
  int write_x  = ((long long)out_size >= x_elems);
  float* out_x = (has_loss && write_x) ? out + 1 : out;

  cudaFuncSetAttribute((const void*)z_kernel,
                       cudaFuncAttributeMaxDynamicSharedMemorySize, SMEM_Z);
  cudaFuncSetAttribute((const void*)x_kernel,
                       cudaFuncAttributeMaxDynamicSharedMemorySize, SMEM_X);

  build_kernel<<<64, 256>>>(biadj, eps, chi);
  z_kernel<<<NBLK, 512, SMEM_Z>>>(idx, kz0, kz1);
  x_kernel<<<NBLK, 512, SMEM_X>>>(idx, out_x, write_x, has_loss, kx0, kx1);
  if (has_loss) fin_kernel<<<1, NBLK>>>(out);
}

// round 16
// speedup vs baseline: 1.2360x; 1.1848x over previous
#include <cuda_runtime.h>
#include <math.h>

// ---------------------------------------------------------------------------
// ERBM CD-1 sweep, bit-matched to JAX (threefry2x32, partitionable RNG).
// R15: fused z+x kernel; gather indices packed 2-bit in registers (no LDS
// idx chain); z-codes exchanged via conflict-free padded smem; 2 CTAs/SM.
// Decision logic (threefry, gumbel logf, f32x2 accumulation order, TwoSum
// fallback) is bit-identical to the passing R11 kernel.
// ---------------------------------------------------------------------------

#define S_TOTAL 65536
#define XDIM 128
#define ZDIM 128
#define S_TILE 128
#define CHUNK 8
#define NCHUNK 16
#define NBLK (S_TOTAL / S_TILE)
#define GAP_THR 1e-2f

#define SK_BYTES (CHUNK * 128 * 64)   // 65536
#define CODE_PITCH 132
#define CODE_OFF SK_BYTES
#define SMEM_TOT (SK_BYTES + 128 * CODE_PITCH)  // 82432

__device__ float g_Kz[ZDIM * XDIM * 16];  // [((z*128+x)*4+a)*4+b]
__device__ float g_Kx[XDIM * ZDIM * 16];  // [((x*128+z)*4+b)*4+a]
__device__ double g_blocksum[NBLK];

// packed dual f32 add, round-to-nearest per lane: bit-identical to 2x FADD.RN
__device__ __forceinline__ void padd(unsigned long long& a, unsigned long long b) {
  asm("add.rn.f32x2 %0, %0, %1;" : "+l"(a) : "l"(b));
}
__device__ __forceinline__ float plo(unsigned long long a) {
  return __uint_as_float((unsigned)a);
}
__device__ __forceinline__ float phi(unsigned long long a) {
  return __uint_as_float((unsigned)(a >> 32));
}

// ---------------------------------------------------------------------------
// threefry2x32 (JAX/Random123, 20 rounds)
// ---------------------------------------------------------------------------
__host__ __device__ __forceinline__ void tf2x32(unsigned k0, unsigned k1,
                                                unsigned c0, unsigned c1,
                                                unsigned& o0, unsigned& o1) {
  unsigned ks2 = k0 ^ k1 ^ 0x1BD11BDAu;
  unsigned x0 = c0 + k0, x1 = c1 + k1;
#define TF_R(r) { x0 += x1; x1 = (x1 << (r)) | (x1 >> (32 - (r))); x1 ^= x0; }
  TF_R(13) TF_R(15) TF_R(26) TF_R(6)
  x0 += k1;  x1 += ks2 + 1u;
  TF_R(17) TF_R(29) TF_R(16) TF_R(24)
  x0 += ks2; x1 += k0 + 2u;
  TF_R(13) TF_R(15) TF_R(26) TF_R(6)
  x0 += k0;  x1 += k1 + 3u;
  TF_R(17) TF_R(29) TF_R(16) TF_R(24)
  x0 += k1;  x1 += ks2 + 4u;
  TF_R(13) TF_R(15) TF_R(26) TF_R(6)
  x0 += ks2; x1 += k0 + 5u;
#undef TF_R
  o0 = x0; o1 = x1;
}

__device__ __forceinline__ float jax_gumbel(unsigned k0, unsigned k1, unsigned idx) {
  unsigned o0, o1;
  tf2x32(k0, k1, 0u, idx, o0, o1);
  unsigned bits = o0 ^ o1;
  float u = __uint_as_float(0x3f800000u | (bits >> 9)) - 1.0f;
  u = fmaxf(u, 1.1754943508222875e-38f);
  return -logf(-logf(u));
}

__device__ __forceinline__ void two_sum(float& hi, float& lo, float v) {
  float s = hi + v;
  float bv = s - hi;
  float err = (hi - (s - bv)) + (v - bv);
  lo += err;
  hi = s;
}

// extract 2-bit code for position p (0..127) from pack
__device__ __forceinline__ int pk_get(const unsigned* pk, int p) {
  return (pk[p >> 4] >> ((p & 15) * 2)) & 3;
}

// ---------------------------------------------------------------------------
__global__ void build_kernel(const float* __restrict__ biadj,
                             const float* __restrict__ eps,
                             const float* __restrict__ chi) {
  int t = blockIdx.x * blockDim.x + threadIdx.x;
  if (t >= XDIM * ZDIM) return;
  int X = t >> 7, Z = t & 127;
  int lx = X >> 1, dx = X & 1, lz = Z >> 1, dz = Z & 1;
  float c[3];
#pragma unroll
  for (int k = 0; k < 3; k++) {
    float acc = 0.f;
#pragma unroll
    for (int b = 0; b < 8; b++)
      acc = fmaf(biadj[(lx * 64 + lz) * 8 + b],
                 eps[((b * 3 + k) * 2 + dx) * 2 + dz], acc);
    c[k] = acc;
  }
#pragma unroll
  for (int a = 0; a < 4; a++)
#pragma unroll
    for (int b = 0; b < 4; b++) {
      float v = 0.f;
#pragma unroll
      for (int k = 0; k < 3; k++) v = fmaf(c[k], chi[(a * 4 + b) * 3 + k], v);
      g_Kz[((Z * 128 + X) * 4 + a) * 4 + b] = v;
      g_Kx[((X * 128 + Z) * 4 + b) * 4 + a] = v;
    }
}

// ---------------------------------------------------------------------------
// Fused sweep: z-phase then x-phase, block = 128 samples, 512 threads.
// ---------------------------------------------------------------------------
__global__ __launch_bounds__(512, 2) void sweep_kernel(
    const int* __restrict__ x0_idx, float* __restrict__ out_x,
    int write_x, int has_loss,
    unsigned kz0, unsigned kz1, unsigned kx0, unsigned kx1) {
  extern __shared__ unsigned char smem[];
  float* sK = (float*)smem;
  unsigned char* sCode = smem + CODE_OFF;   // [pos-owner s][132]
  int t = threadIdx.x;
  int s0 = blockIdx.x * S_TILE;
  int s_local = t & 127, g = t >> 7;
  int s = s0 + s_local;

  // ---- load this sample's 128 x0 indices into 8 packed u32 registers ----
  unsigned ip[8];
  {
    const int4* row = (const int4*)(x0_idx + (size_t)s * XDIM);
#pragma unroll
    for (int j = 0; j < 8; j++) {
      unsigned p = 0;
#pragma unroll
      for (int q = 0; q < 4; q++) {
        int4 v = row[j * 4 + q];
        p |= ((unsigned)(v.x & 3)) << ((q * 4 + 0) * 2);
        p |= ((unsigned)(v.y & 3)) << ((q * 4 + 1) * 2);
        p |= ((unsigned)(v.z & 3)) << ((q * 4 + 2) * 2);
        p |= ((unsigned)(v.w & 3)) << ((q * 4 + 3) * 2);
      }
      ip[j] = p;
    }
  }

  // ======================= Z PHASE =======================
  for (int c = 0; c < NCHUNK; c++) {
    __syncthreads();
    {
      const float4* src = (const float4*)(g_Kz + (size_t)c * CHUNK * XDIM * 16);
      float4* dst = (float4*)sK;
#pragma unroll
      for (int r = 0; r < 8; r++) dst[t + r * 512] = src[t + r * 512];
    }
    __syncthreads();

    const char* base0 = (const char*)sK + (g * 2) * (XDIM * 64);
    const char* base1 = base0 + XDIM * 64;
    unsigned long long a00 = 0, a01 = 0, a10 = 0, a11 = 0;
#pragma unroll
    for (int j = 0; j < 8; j++) {
      unsigned u = ip[j];
      const char* p0 = base0 + j * 16 * 64;
      const char* p1 = base1 + j * 16 * 64;
#pragma unroll 4
      for (int k = 0; k < 16; k++) {
        int off = k * 64 + (int)(((u >> (2 * k)) & 3u) << 4);
        ulonglong2 v0 = *(const ulonglong2*)(p0 + off);
        ulonglong2 v1 = *(const ulonglong2*)(p1 + off);
        padd(a00, v0.x); padd(a01, v0.y);
        padd(a10, v1.x); padd(a11, v1.y);
      }
    }

#pragma unroll
    for (int zz = 0; zz < 2; zz++) {
      int zc = g * 2 + zz;
      int z = c * CHUNK + zc;
      float ez[4];
      if (zz == 0) { ez[0] = plo(a00); ez[1] = phi(a00); ez[2] = plo(a01); ez[3] = phi(a01); }
      else         { ez[0] = plo(a10); ez[1] = phi(a10); ez[2] = plo(a11); ez[3] = phi(a11); }
      unsigned base = ((unsigned)(s * ZDIM + z)) * 4u;
      float gq[4], sc[4];
#pragma unroll
      for (int b = 0; b < 4; b++) {
        gq[b] = jax_gumbel(kz0, kz1, base + (unsigned)b);
        sc[b] = gq[b] - ez[b];
      }
      int bi = 0;
#pragma unroll
      for (int b = 1; b < 4; b++) if (sc[b] > sc[bi]) bi = b;
      float second = -3.4e38f;
#pragma unroll
      for (int b = 0; b < 4; b++) if (b != bi && sc[b] > second) second = sc[b];

      if (sc[bi] - second < GAP_THR) {
        float hi[4] = {0.f,0.f,0.f,0.f}, lo[4] = {0.f,0.f,0.f,0.f};
        const char* bb = (const char*)sK + zc * (XDIM * 64);
        for (int x = 0; x < XDIM; x++) {
          int off = x * 64 + (pk_get(ip, x) << 4);
          const float* p = (const float*)(bb + off);
#pragma unroll
          for (int b = 0; b < 4; b++) two_sum(hi[b], lo[b], p[b]);
        }
        float sce[4];
#pragma unroll
        for (int b = 0; b < 4; b++) sce[b] = gq[b] - (hi[b] + lo[b]);
        bi = 0;
#pragma unroll
        for (int b = 1; b < 4; b++) if (sce[b] > sce[bi]) bi = b;
      }
      sCode[s_local * CODE_PITCH + z] = (unsigned char)bi;
    }
  }

  __syncthreads();  // all z codes staged

  // ---- repack this sample's 128 z-codes into 8 u32 registers ----
  unsigned zp[8];
  {
    const unsigned* w = (const unsigned*)(sCode + s_local * CODE_PITCH);
#pragma unroll
    for (int j = 0; j < 8; j++) {
      unsigned p = 0;
#pragma unroll
      for (int q = 0; q < 4; q++) {
        unsigned v = w[j * 4 + q];
        p |= (v & 3u) << ((q * 4 + 0) * 2);
        p |= ((v >> 8) & 3u) << ((q * 4 + 1) * 2);
        p |= ((v >> 16) & 3u) << ((q * 4 + 2) * 2);
        p |= ((v >> 24) & 3u) << ((q * 4 + 3) * 2);
      }
      zp[j] = p;
    }
  }

  // ======================= X PHASE =======================
  double lsum = 0.0;
  for (int c = 0; c < NCHUNK; c++) {
    __syncthreads();
    {
      const float4* src = (const float4*)(g_Kx + (size_t)c * CHUNK * ZDIM * 16);
      float4* dst = (float4*)sK;
#pragma unroll
      for (int r = 0; r < 8; r++) dst[t + r * 512] = src[t + r * 512];
    }
    __syncthreads();

    const char* base0 = (const char*)sK + (g * 2) * (ZDIM * 64);
    const char* base1 = base0 + ZDIM * 64;
    unsigned long long a00 = 0, a01 = 0, a10 = 0, a11 = 0;
#pragma unroll
    for (int j = 0; j < 8; j++) {
      unsigned u = zp[j];
      const char* p0 = base0 + j * 16 * 64;
      const char* p1 = base1 + j * 16 * 64;
#pragma unroll 4
      for (int k = 0; k < 16; k++) {
        int off = k * 64 + (int)(((u >> (2 * k)) & 3u) << 4);
        ulonglong2 v0 = *(const ulonglong2*)(p0 + off);
        ulonglong2 v1 = *(const ulonglong2*)(p1 + off);
        padd(a00, v0.x); padd(a01, v0.y);
        padd(a10, v1.x); padd(a11, v1.y);
      }
    }

#pragma unroll
    for (int xx = 0; xx < 2; xx++) {
      int xc = g * 2 + xx;
      int x = c * CHUNK + xc;
      float ex[4];
      if (xx == 0) { ex[0] = plo(a00); ex[1] = phi(a00); ex[2] = plo(a01); ex[3] = phi(a01); }
      else         { ex[0] = plo(a10); ex[1] = phi(a10); ex[2] = plo(a11); ex[3] = phi(a11); }
      unsigned base = ((unsigned)(s * XDIM + x)) * 4u;
      float gq[4], sc[4];
#pragma unroll
      for (int a = 0; a < 4; a++) {
        gq[a] = jax_gumbel(kx0, kx1, base + (unsigned)a);
        sc[a] = gq[a] - ex[a];
      }
      int a1 = 0;
#pragma unroll
      for (int a = 1; a < 4; a++) if (sc[a] > sc[a1]) a1 = a;
      float second = -3.4e38f;
#pragma unroll
      for (int a = 0; a < 4; a++) if (a != a1 && sc[a] > second) second = sc[a];

      if (sc[a1] - second < GAP_THR) {
        float hi[4] = {0.f,0.f,0.f,0.f}, lo[4] = {0.f,0.f,0.f,0.f};
        const char* bb = (const char*)sK + xc * (ZDIM * 64);
        for (int z = 0; z < ZDIM; z++) {
          int off = z * 64 + (pk_get(zp, z) << 4);
          const float* p = (const float*)(bb + off);
#pragma unroll
          for (int a = 0; a < 4; a++) two_sum(hi[a], lo[a], p[a]);
        }
        float sce[4];
#pragma unroll
        for (int a = 0; a < 4; a++) {
          ex[a] = hi[a] + lo[a];
          sce[a] = gq[a] - ex[a];
        }
        a1 = 0;
#pragma unroll
        for (int a = 1; a < 4; a++) if (sce[a] > sce[a1]) a1 = a;
      }

      sCode[s_local * CODE_PITCH + x] = (unsigned char)a1;
      if (has_loss) {
        int a0 = pk_get(ip, x);
        lsum += (double)(ex[a0] - ex[a1]);
      }
    }
  }

  __syncthreads();  // x codes staged; sK free

  if (write_x) {
    // coalesced: consecutive lanes -> consecutive x within a sample row
    for (int j = t; j < S_TILE * XDIM; j += 512) {
      int sl = j >> 7, x = j & 127;
      int code = sCode[sl * CODE_PITCH + x];
      float* o = out_x + ((size_t)((s0 + sl) * XDIM + x)) * 4;
      o[0] = (code == 0) ? 1.f : 0.f;
      o[1] = (code == 1) ? 1.f : 0.f;
      o[2] = (code == 2) ? 1.f : 0.f;
      o[3] = (code == 3) ? 1.f : 0.f;
    }
  }

  if (has_loss) {
    double* red = (double*)smem;  // overlays sK (done)
    red[t] = lsum;
    __syncthreads();
    for (int st = 256; st > 0; st >>= 1) {
      if (t < st) red[t] += red[t + st];
      __syncthreads();
    }
    if (t == 0) g_blocksum[blockIdx.x] = red[0];
  }
}

__global__ void fin_kernel(float* __restrict__ out) {
  __shared__ double red[NBLK];
  int t = threadIdx.x;
  red[t] = g_blocksum[t];
  __syncthreads();
  for (int st = NBLK / 2; st > 0; st >>= 1) {
    if (t < st) red[t] += red[t + st];
    __syncthreads();
  }
  if (t == 0) out[0] = (float)(red[0] / 65536.0);
}

// ---------------------------------------------------------------------------
extern "C" void kernel_launch(void* const* d_in, const int* in_sizes, int n_in,
                              void* d_out, int out_size) {
  const float* biadj = (const float*)d_in[0];
  const float* eps   = (const float*)d_in[1];
  const float* chi   = (const float*)d_in[2];
  const int*   idx   = (const int*)d_in[3];
  float* out = (float*)d_out;

  unsigned kz0, kz1, kx0, kx1;
  tf2x32(0u, 42u, 0u, 0u, kz0, kz1);
  tf2x32(0u, 42u, 0u, 1u, kx0, kx1);

  const long long x_elems = (long long)S_TOTAL * XDIM * 4;
  int has_loss = (out_size != (int)x_elems);
  int write_x  = ((long long)out_size >= x_elems);
  float* out_x = (has_loss && write_x) ? out + 1 : out;

  cudaFuncSetAttribute((const void*)sweep_kernel,
                       cudaFuncAttributeMaxDynamicSharedMemorySize, SMEM_TOT);

  build_kernel<<<64, 256>>>(biadj, eps, chi);
  sweep_kernel<<<NBLK, 512, SMEM_TOT>>>(idx, out_x, write_x, has_loss,
                                        kz0, kz1, kx0, kx1);
  if (has_loss) fin_kernel<<<1, NBLK>>>(out);
}